// round 3
// baseline (speedup 1.0000x reference)
#include <cuda_runtime.h>
#include <cuda_bf16.h>

#define NV   100000
#define ND   128
#define NE   600000
#define NVD  (NV * ND)
#define NTB  1024
#define NB   ((NV + NTB - 1) / NTB)   // 98

// ---------------- scratch (device globals: no allocation allowed) ------------
__device__ float g_f[NVD];      // activations between layers
__device__ float g_h0[NVD];     // W0 branch
__device__ float g_y[NVD];      // W1 branch (gathered over edges)
__device__ float g_h[NVD];      // pre-BN result
__device__ int   g_deg[NV];
__device__ int   g_rowptr[NV + 1];
__device__ int   g_cursor[NV];
__device__ int   g_adj[2 * NE];
__device__ float g_stats[2 * ND];   // sum | sumsq
__device__ float g_mr[2 * ND];      // mean | rstd
__device__ int   g_is64;
__device__ int   g_bsum[NB];
__device__ int   g_boff[NB];
__device__ float2 g_Wd[4 * 2 * ND * ND];   // duplicated weights (w,w), 1MB

// ---------------- edge dtype probe ------------------------------------------
__global__ void k_detect(const void* __restrict__ edges) {
    const long long* e = (const long long*)edges;
    int ok = 1;
    for (int i = 0; i < 16; i++) {
        long long v = e[i];
        if (v < 0 || v >= NV) ok = 0;
    }
    g_is64 = ok;
}

__device__ __forceinline__ void load_edge(const void* edges, int e, int& a, int& b) {
    if (g_is64) {
        longlong2 p = ((const longlong2*)edges)[e];
        a = (int)p.x; b = (int)p.y;
    } else {
        int2 p = ((const int2*)edges)[e];
        a = p.x; b = p.y;
    }
}

// ---------------- CSR build --------------------------------------------------
__global__ void k_zero_deg() {
    int i = blockIdx.x * blockDim.x + threadIdx.x;
    if (i < NV) g_deg[i] = 0;
}

__global__ void k_count(const void* __restrict__ edges) {
    int e = blockIdx.x * blockDim.x + threadIdx.x;
    if (e < NE) {
        int a, b;
        load_edge(edges, e, a, b);
        atomicAdd(&g_deg[a], 1);
        atomicAdd(&g_deg[b], 1);
    }
}

// block sums of g_deg (grid NB, 1024 thr)
__global__ void k_bsum() {
    __shared__ int ws[32];
    int t = threadIdx.x, lane = t & 31, wid = t >> 5;
    int idx = blockIdx.x * NTB + t;
    int v = (idx < NV) ? g_deg[idx] : 0;
    #pragma unroll
    for (int off = 16; off > 0; off >>= 1)
        v += __shfl_down_sync(0xFFFFFFFFu, v, off);
    if (lane == 0) ws[wid] = v;
    __syncthreads();
    if (wid == 0) {
        int s = ws[lane];
        #pragma unroll
        for (int off = 16; off > 0; off >>= 1)
            s += __shfl_down_sync(0xFFFFFFFFu, s, off);
        if (lane == 0) g_bsum[blockIdx.x] = s;
    }
}

// scan 98 block sums (1 block, 128 thr)
__global__ void k_bscan() {
    __shared__ int ws[4];
    int t = threadIdx.x, lane = t & 31, wid = t >> 5;
    int v = (t < NB) ? g_bsum[t] : 0;
    int inc = v;
    #pragma unroll
    for (int off = 1; off < 32; off <<= 1) {
        int x = __shfl_up_sync(0xFFFFFFFFu, inc, off);
        if (lane >= off) inc += x;
    }
    if (lane == 31) ws[wid] = inc;
    __syncthreads();
    int woff = 0;
    for (int w = 0; w < wid; w++) woff += ws[w];
    if (t < NB) g_boff[t] = woff + inc - v;
    if (t == 0) g_rowptr[NV] = 2 * NE;
}

// apply: full exclusive scan -> rowptr, cursor (grid NB, 1024 thr)
__global__ void k_apply() {
    __shared__ int ws[32];
    int t = threadIdx.x, lane = t & 31, wid = t >> 5;
    int idx = blockIdx.x * NTB + t;
    int v = (idx < NV) ? g_deg[idx] : 0;
    int inc = v;
    #pragma unroll
    for (int off = 1; off < 32; off <<= 1) {
        int x = __shfl_up_sync(0xFFFFFFFFu, inc, off);
        if (lane >= off) inc += x;
    }
    if (lane == 31) ws[wid] = inc;
    __syncthreads();
    if (wid == 0) {
        int s = ws[lane];
        #pragma unroll
        for (int off = 1; off < 32; off <<= 1) {
            int x = __shfl_up_sync(0xFFFFFFFFu, s, off);
            if (lane >= off) s += x;
        }
        ws[lane] = s;
    }
    __syncthreads();
    int excl = g_boff[blockIdx.x] + ((wid > 0) ? ws[wid - 1] : 0) + inc - v;
    if (idx < NV) { g_rowptr[idx] = excl; g_cursor[idx] = excl; }
}

__global__ void k_fill(const void* __restrict__ edges) {
    int e = blockIdx.x * blockDim.x + threadIdx.x;
    if (e < NE) {
        int a, b;
        load_edge(edges, e, a, b);
        int pa = atomicAdd(&g_cursor[a], 1);
        g_adj[pa] = b;
        int pb = atomicAdd(&g_cursor[b], 1);
        g_adj[pb] = a;
    }
}

// ---------------- weight duplication: g_Wd[(s*ND + k)*ND + n] = (W[n][k],)x2 --
__global__ void k_wdup(const float* __restrict__ W0, const float* __restrict__ W1) {
    int i = blockIdx.x * blockDim.x + threadIdx.x;   // over 8*128*128
    if (i >= 8 * ND * ND) return;
    int n = i & (ND - 1);
    int k = (i >> 7) & (ND - 1);
    int s = i >> 14;               // 0..7 = L*2+br
    int L = s >> 1, br = s & 1;
    const float* W = br ? W1 : W0;
    float w = W[(size_t)L * ND * ND + (size_t)n * ND + k];
    g_Wd[i] = make_float2(w, w);
}

// ---------------- GEMM via packed fma.rn.f32x2 -------------------------------
// C[i,j] = sum_k A[i,k]*W[j,k] + bias[j]
#define BM 128
#define BN 128
#define BK 16

__global__ __launch_bounds__(256, 2)
void k_gemm2(const float* __restrict__ A, const float2* __restrict__ Wd,
             const float* __restrict__ bias, float* __restrict__ C) {
    __shared__ float  As[BK][BM];        // 8 KB
    __shared__ float2 BsD[BK][BN];       // 16 KB, duplicated (w,w)
    int tid = threadIdx.x;               // 256
    int rowBase = blockIdx.x * BM;
    int tr = tid >> 4, tc = tid & 15;

    unsigned long long acc[4][8];        // pairs of M-rows x 8 N-cols
    #pragma unroll
    for (int m = 0; m < 4; m++)
        #pragma unroll
        for (int n = 0; n < 8; n++) acc[m][n] = 0ULL;

    for (int k0 = 0; k0 < ND; k0 += BK) {
        // load A tile: 512 float4 slots
        #pragma unroll
        for (int i = 0; i < 2; i++) {
            int s  = i * 256 + tid;
            int r  = s >> 2;
            int kq = (s & 3) << 2;
            float4 av = make_float4(0.f, 0.f, 0.f, 0.f);
            if (rowBase + r < NV)
                av = *(const float4*)(A + (size_t)(rowBase + r) * ND + k0 + kq);
            As[kq + 0][r] = av.x; As[kq + 1][r] = av.y;
            As[kq + 2][r] = av.z; As[kq + 3][r] = av.w;
        }
        // load duplicated W tile: 1024 float4 slots (16 rows x 64 float4)
        #pragma unroll
        for (int i = 0; i < 4; i++) {
            int s   = i * 256 + tid;
            int kk  = s >> 6;
            int q   = s & 63;
            float4 wv = ((const float4*)(Wd + (size_t)(k0 + kk) * ND))[q];
            ((float4*)&BsD[kk][0])[q] = wv;
        }
        __syncthreads();
        #pragma unroll
        for (int k = 0; k < BK; k++) {
            ulonglong2 av0 = *(const ulonglong2*)&As[k][tr * 8];
            ulonglong2 av1 = *(const ulonglong2*)&As[k][tr * 8 + 4];
            unsigned long long a2[4] = {av0.x, av0.y, av1.x, av1.y};
            const ulonglong2* bp = (const ulonglong2*)&BsD[k][tc * 8];
            ulonglong2 b0 = bp[0], b1 = bp[1], b2 = bp[2], b3 = bp[3];
            unsigned long long bd[8] = {b0.x, b0.y, b1.x, b1.y,
                                        b2.x, b2.y, b3.x, b3.y};
            #pragma unroll
            for (int m = 0; m < 4; m++)
                #pragma unroll
                for (int n = 0; n < 8; n++)
                    asm("fma.rn.f32x2 %0, %1, %2, %0;"
                        : "+l"(acc[m][n]) : "l"(a2[m]), "l"(bd[n]));
        }
        __syncthreads();
    }

    float bb[8];
    #pragma unroll
    for (int n = 0; n < 8; n++) bb[n] = __ldg(bias + tc * 8 + n);

    #pragma unroll
    for (int m = 0; m < 4; m++) {
        float lo[8], hi[8];
        #pragma unroll
        for (int n = 0; n < 8; n++)
            asm("mov.b64 {%0,%1}, %2;" : "=f"(lo[n]), "=f"(hi[n]) : "l"(acc[m][n]));
        int row0 = rowBase + tr * 8 + 2 * m;
        if (row0 < NV) {
            float* cp = C + (size_t)row0 * ND + tc * 8;
            ((float4*)cp)[0] = make_float4(lo[0] + bb[0], lo[1] + bb[1],
                                           lo[2] + bb[2], lo[3] + bb[3]);
            ((float4*)cp)[1] = make_float4(lo[4] + bb[4], lo[5] + bb[5],
                                           lo[6] + bb[6], lo[7] + bb[7]);
        }
        if (row0 + 1 < NV) {
            float* cp = C + (size_t)(row0 + 1) * ND + tc * 8;
            ((float4*)cp)[0] = make_float4(hi[0] + bb[0], hi[1] + bb[1],
                                           hi[2] + bb[2], hi[3] + bb[3]);
            ((float4*)cp)[1] = make_float4(hi[4] + bb[4], hi[5] + bb[5],
                                           hi[6] + bb[6], hi[7] + bb[7]);
        }
    }
}

// ---------------- misc -------------------------------------------------------
__global__ void k_zero_stats() {
    int i = threadIdx.x;
    if (i < 2 * ND) g_stats[i] = 0.f;
}

__global__ void k_finalize() {
    int c = threadIdx.x;   // 128
    float mean = g_stats[c] * (1.0f / NV);
    float var  = g_stats[ND + c] * (1.0f / NV) - mean * mean;
    g_mr[c]      = mean;
    g_mr[ND + c] = rsqrtf(var + 1e-5f);
}

// ---------------- aggregate: out[v] = h0[v] + sum_{u in N(v)} y[u] -----------
__global__ void k_agg(const float* __restrict__ h0, const float* __restrict__ y,
                      float* __restrict__ out, int doStats) {
    int lane   = threadIdx.x & 31;
    int warp   = (blockIdx.x * blockDim.x + threadIdx.x) >> 5;
    int nwarps = (gridDim.x * blockDim.x) >> 5;

    float4 csum = make_float4(0.f, 0.f, 0.f, 0.f);
    float4 csq  = make_float4(0.f, 0.f, 0.f, 0.f);

    for (int v = warp; v < NV; v += nwarps) {
        float4 acc = ((const float4*)(h0 + (size_t)v * ND))[lane];
        int beg = g_rowptr[v], end = g_rowptr[v + 1];
        int j = beg;
        for (; j + 3 < end; j += 4) {
            int u0 = g_adj[j], u1 = g_adj[j + 1];
            int u2 = g_adj[j + 2], u3 = g_adj[j + 3];
            float4 a0 = ((const float4*)(y + (size_t)u0 * ND))[lane];
            float4 a1 = ((const float4*)(y + (size_t)u1 * ND))[lane];
            float4 a2 = ((const float4*)(y + (size_t)u2 * ND))[lane];
            float4 a3 = ((const float4*)(y + (size_t)u3 * ND))[lane];
            acc.x += (a0.x + a1.x) + (a2.x + a3.x);
            acc.y += (a0.y + a1.y) + (a2.y + a3.y);
            acc.z += (a0.z + a1.z) + (a2.z + a3.z);
            acc.w += (a0.w + a1.w) + (a2.w + a3.w);
        }
        for (; j < end; j++) {
            int u0 = g_adj[j];
            float4 a0 = ((const float4*)(y + (size_t)u0 * ND))[lane];
            acc.x += a0.x; acc.y += a0.y; acc.z += a0.z; acc.w += a0.w;
        }
        ((float4*)(out + (size_t)v * ND))[lane] = acc;
        if (doStats) {
            csum.x += acc.x; csum.y += acc.y; csum.z += acc.z; csum.w += acc.w;
            csq.x += acc.x * acc.x; csq.y += acc.y * acc.y;
            csq.z += acc.z * acc.z; csq.w += acc.w * acc.w;
        }
    }
    if (doStats) {
        int c = lane * 4;
        atomicAdd(&g_stats[c + 0], csum.x);
        atomicAdd(&g_stats[c + 1], csum.y);
        atomicAdd(&g_stats[c + 2], csum.z);
        atomicAdd(&g_stats[c + 3], csum.w);
        atomicAdd(&g_stats[ND + c + 0], csq.x);
        atomicAdd(&g_stats[ND + c + 1], csq.y);
        atomicAdd(&g_stats[ND + c + 2], csq.z);
        atomicAdd(&g_stats[ND + c + 3], csq.w);
    }
}

// ---------------- BN normalize + optional residual + ReLU --------------------
__global__ void k_norm(const float* __restrict__ h, float* __restrict__ f,
                       const float* __restrict__ gamma, const float* __restrict__ beta,
                       const float* __restrict__ res) {
    int i = blockIdx.x * blockDim.x + threadIdx.x;   // float4 index
    if (i >= NVD / 4) return;
    int col4 = i & (ND / 4 - 1);
    float4 hv = ((const float4*)h)[i];
    float4 mu = ((const float4*)g_mr)[col4];
    float4 rs = ((const float4*)(g_mr + ND))[col4];
    float4 ga = __ldg((const float4*)gamma + col4);
    float4 be = __ldg((const float4*)beta + col4);
    float4 o;
    o.x = (hv.x - mu.x) * rs.x * ga.x + be.x;
    o.y = (hv.y - mu.y) * rs.y * ga.y + be.y;
    o.z = (hv.z - mu.z) * rs.z * ga.z + be.z;
    o.w = (hv.w - mu.w) * rs.w * ga.w + be.w;
    if (res) {
        float4 rv = ((const float4*)res)[i];
        o.x += rv.x; o.y += rv.y; o.z += rv.z; o.w += rv.w;
    }
    o.x = fmaxf(o.x, 0.f); o.y = fmaxf(o.y, 0.f);
    o.z = fmaxf(o.z, 0.f); o.w = fmaxf(o.w, 0.f);
    ((float4*)f)[i] = o;
}

// ---------------- launch -----------------------------------------------------
extern "C" void kernel_launch(void* const* d_in, const int* in_sizes, int n_in,
                              void* d_out, int out_size) {
    const float* feat  = (const float*)d_in[0];
    const void*  edges = d_in[1];
    const float* W0    = (const float*)d_in[2];
    const float* b0    = (const float*)d_in[3];
    const float* W1    = (const float*)d_in[4];
    const float* b1    = (const float*)d_in[5];
    const float* gamma = (const float*)d_in[6];
    const float* beta  = (const float*)d_in[7];
    float*       out   = (float*)d_out;

    float*  pf;  cudaGetSymbolAddress((void**)&pf,  g_f);
    float*  ph0; cudaGetSymbolAddress((void**)&ph0, g_h0);
    float*  py;  cudaGetSymbolAddress((void**)&py,  g_y);
    float*  ph;  cudaGetSymbolAddress((void**)&ph,  g_h);
    float2* pwd; cudaGetSymbolAddress((void**)&pwd, g_Wd);

    // CSR build + weight duplication (once per call)
    k_detect<<<1, 1>>>(edges);
    k_zero_deg<<<(NV + 255) / 256, 256>>>();
    k_wdup<<<(8 * ND * ND + 255) / 256, 256>>>(W0, W1);
    k_count<<<(NE + 255) / 256, 256>>>(edges);
    k_bsum<<<NB, NTB>>>();
    k_bscan<<<1, 128>>>();
    k_apply<<<NB, NTB>>>();
    k_fill<<<(NE + 255) / 256, 256>>>(edges);

    const int gemmBlocks = (NV + BM - 1) / BM;   // 782
    const float* x = feat;
    for (int L = 0; L < 4; L++) {
        const float2* wd0 = pwd + (size_t)(L * 2 + 0) * ND * ND;
        const float2* wd1 = pwd + (size_t)(L * 2 + 1) * ND * ND;
        k_gemm2<<<gemmBlocks, 256>>>(x, wd0, b0 + L * ND, ph0);
        k_gemm2<<<gemmBlocks, 256>>>(x, wd1, b1 + L * ND, py);
        if (L < 3) {
            k_zero_stats<<<1, 256>>>();
            k_agg<<<2048, 256>>>(ph0, py, ph, 1);
            k_finalize<<<1, ND>>>();
            const float* res = (L == 2) ? feat : nullptr;
            k_norm<<<(NVD / 4 + 255) / 256, 256>>>(ph, pf, gamma + L * ND,
                                                   beta + L * ND, res);
            x = pf;
        } else {
            k_agg<<<2048, 256>>>(ph0, py, out, 0);
        }
    }
}

// round 4
// speedup vs baseline: 1.5903x; 1.5903x over previous
#include <cuda_runtime.h>
#include <cuda_bf16.h>

#define NV   100000
#define ND   128
#define NE   600000
#define NVD  (NV * ND)
#define NTB  1024
#define NB   ((NV + NTB - 1) / NTB)   // 98

// ---------------- scratch (device globals: no allocation allowed) ------------
__device__ float g_f[NVD];      // activations between layers
__device__ float g_h0[NVD];     // W0 branch
__device__ float g_y[NVD];      // W1 branch (gathered over edges)
__device__ float g_h[NVD];      // pre-BN result
__device__ int   g_deg[NV];
__device__ int   g_rowptr[NV + 1];
__device__ int   g_cursor[NV];
__device__ int   g_adj[2 * NE];
__device__ float g_stats[2 * ND];   // sum | sumsq
__device__ float g_mr[2 * ND];      // mean | rstd
__device__ int   g_is64;
__device__ int   g_bsum[NB];
__device__ int   g_boff[NB];
__device__ __nv_bfloat16 g_Whi[8 * ND * ND];  // split weights, [s][n][k]
__device__ __nv_bfloat16 g_Wlo[8 * ND * ND];

// ---------------- edge dtype probe ------------------------------------------
__global__ void k_detect(const void* __restrict__ edges) {
    const long long* e = (const long long*)edges;
    int ok = 1;
    for (int i = 0; i < 16; i++) {
        long long v = e[i];
        if (v < 0 || v >= NV) ok = 0;
    }
    g_is64 = ok;
}

__device__ __forceinline__ void load_edge(const void* edges, int e, int& a, int& b) {
    if (g_is64) {
        longlong2 p = ((const longlong2*)edges)[e];
        a = (int)p.x; b = (int)p.y;
    } else {
        int2 p = ((const int2*)edges)[e];
        a = p.x; b = p.y;
    }
}

// ---------------- CSR build --------------------------------------------------
__global__ void k_zero_deg() {
    int i = blockIdx.x * blockDim.x + threadIdx.x;
    if (i < NV) g_deg[i] = 0;
}

__global__ void k_count(const void* __restrict__ edges) {
    int e = blockIdx.x * blockDim.x + threadIdx.x;
    if (e < NE) {
        int a, b;
        load_edge(edges, e, a, b);
        atomicAdd(&g_deg[a], 1);
        atomicAdd(&g_deg[b], 1);
    }
}

__global__ void k_bsum() {
    __shared__ int ws[32];
    int t = threadIdx.x, lane = t & 31, wid = t >> 5;
    int idx = blockIdx.x * NTB + t;
    int v = (idx < NV) ? g_deg[idx] : 0;
    #pragma unroll
    for (int off = 16; off > 0; off >>= 1)
        v += __shfl_down_sync(0xFFFFFFFFu, v, off);
    if (lane == 0) ws[wid] = v;
    __syncthreads();
    if (wid == 0) {
        int s = ws[lane];
        #pragma unroll
        for (int off = 16; off > 0; off >>= 1)
            s += __shfl_down_sync(0xFFFFFFFFu, s, off);
        if (lane == 0) g_bsum[blockIdx.x] = s;
    }
}

__global__ void k_bscan() {
    __shared__ int ws[4];
    int t = threadIdx.x, lane = t & 31, wid = t >> 5;
    int v = (t < NB) ? g_bsum[t] : 0;
    int inc = v;
    #pragma unroll
    for (int off = 1; off < 32; off <<= 1) {
        int x = __shfl_up_sync(0xFFFFFFFFu, inc, off);
        if (lane >= off) inc += x;
    }
    if (lane == 31) ws[wid] = inc;
    __syncthreads();
    int woff = 0;
    for (int w = 0; w < wid; w++) woff += ws[w];
    if (t < NB) g_boff[t] = woff + inc - v;
    if (t == 0) g_rowptr[NV] = 2 * NE;
}

__global__ void k_apply() {
    __shared__ int ws[32];
    int t = threadIdx.x, lane = t & 31, wid = t >> 5;
    int idx = blockIdx.x * NTB + t;
    int v = (idx < NV) ? g_deg[idx] : 0;
    int inc = v;
    #pragma unroll
    for (int off = 1; off < 32; off <<= 1) {
        int x = __shfl_up_sync(0xFFFFFFFFu, inc, off);
        if (lane >= off) inc += x;
    }
    if (lane == 31) ws[wid] = inc;
    __syncthreads();
    if (wid == 0) {
        int s = ws[lane];
        #pragma unroll
        for (int off = 1; off < 32; off <<= 1) {
            int x = __shfl_up_sync(0xFFFFFFFFu, s, off);
            if (lane >= off) s += x;
        }
        ws[lane] = s;
    }
    __syncthreads();
    int excl = g_boff[blockIdx.x] + ((wid > 0) ? ws[wid - 1] : 0) + inc - v;
    if (idx < NV) { g_rowptr[idx] = excl; g_cursor[idx] = excl; }
}

__global__ void k_fill(const void* __restrict__ edges) {
    int e = blockIdx.x * blockDim.x + threadIdx.x;
    if (e < NE) {
        int a, b;
        load_edge(edges, e, a, b);
        int pa = atomicAdd(&g_cursor[a], 1);
        g_adj[pa] = b;
        int pb = atomicAdd(&g_cursor[b], 1);
        g_adj[pb] = a;
    }
}

// ---------------- weight split into bf16 hi/lo -------------------------------
// layout: g_Whi[((L*2+br)*ND + n)*ND + k] from W[L][n][k]
__global__ void k_wsplit(const float* __restrict__ W0, const float* __restrict__ W1) {
    int i = blockIdx.x * blockDim.x + threadIdx.x;
    if (i >= 8 * ND * ND) return;
    int s = i >> 14;             // 0..7
    int L = s >> 1, br = s & 1;
    int nk = i & (ND * ND - 1);
    const float* W = br ? W1 : W0;
    float w = W[(size_t)L * ND * ND + nk];
    __nv_bfloat16 hi = __float2bfloat16_rn(w);
    __nv_bfloat16 lo = __float2bfloat16_rn(w - __bfloat162float(hi));
    g_Whi[i] = hi;
    g_Wlo[i] = lo;
}

// ---------------- tensor-core GEMM: C[i,j] = sum_k A[i,k]*W[j,k] + b[j] ------
// double-bf16 split: C = Ahi*Bhi + Ahi*Blo + Alo*Bhi
#define BM 128
#define BK 32
#define LDA 40          // padded halves per row -> conflict-free frag loads

__device__ __forceinline__ void mma_bf16(float* c, const unsigned* a, const unsigned* b) {
    asm volatile(
        "mma.sync.aligned.m16n8k16.row.col.f32.bf16.bf16.f32 "
        "{%0,%1,%2,%3}, {%4,%5,%6,%7}, {%8,%9}, {%0,%1,%2,%3};"
        : "+f"(c[0]), "+f"(c[1]), "+f"(c[2]), "+f"(c[3])
        : "r"(a[0]), "r"(a[1]), "r"(a[2]), "r"(a[3]), "r"(b[0]), "r"(b[1]));
}

__global__ __launch_bounds__(256, 2)
void k_gemm_tc(const float* __restrict__ A,
               const __nv_bfloat16* __restrict__ Whi,
               const __nv_bfloat16* __restrict__ Wlo,
               const float* __restrict__ bias, float* __restrict__ C) {
    __shared__ __nv_bfloat16 As_hi[BM][LDA];
    __shared__ __nv_bfloat16 As_lo[BM][LDA];
    __shared__ __nv_bfloat16 Bs_hi[ND][LDA];
    __shared__ __nv_bfloat16 Bs_lo[ND][LDA];

    int tid = threadIdx.x;            // 256
    int w   = tid >> 5;               // warp 0..7  -> rows [16w,16w+16)
    int lane = tid & 31;
    int qr = lane >> 2, qc = lane & 3;
    int rowBase = blockIdx.x * BM;

    float acc[16][4];
    #pragma unroll
    for (int nt = 0; nt < 16; nt++)
        #pragma unroll
        for (int j = 0; j < 4; j++) acc[nt][j] = 0.f;

    for (int k0 = 0; k0 < ND; k0 += BK) {
        // stage A tile [128][32] fp32 -> split bf16 hi/lo
        #pragma unroll
        for (int i = 0; i < 4; i++) {
            int s = i * 256 + tid;          // 1024 float4 slots
            int r = s >> 3;
            int q = s & 7;                  // float4 within row
            float4 av = make_float4(0.f, 0.f, 0.f, 0.f);
            if (rowBase + r < NV)
                av = *(const float4*)(A + (size_t)(rowBase + r) * ND + k0 + q * 4);
            float vv[4] = {av.x, av.y, av.z, av.w};
            __nv_bfloat16 h[4], l[4];
            #pragma unroll
            for (int j = 0; j < 4; j++) {
                h[j] = __float2bfloat16_rn(vv[j]);
                l[j] = __float2bfloat16_rn(vv[j] - __bfloat162float(h[j]));
            }
            *(__nv_bfloat162*)&As_hi[r][q * 4]     = __nv_bfloat162{h[0], h[1]};
            *(__nv_bfloat162*)&As_hi[r][q * 4 + 2] = __nv_bfloat162{h[2], h[3]};
            *(__nv_bfloat162*)&As_lo[r][q * 4]     = __nv_bfloat162{l[0], l[1]};
            *(__nv_bfloat162*)&As_lo[r][q * 4 + 2] = __nv_bfloat162{l[2], l[3]};
        }
        // stage W tile [128 n][32 k] bf16 (pre-split)
        #pragma unroll
        for (int i = 0; i < 2; i++) {
            int s = i * 256 + tid;          // 512 uint4 slots
            int n = s >> 2;
            int q = s & 3;                  // uint4 (8 halves) within row
            uint4 hv = *(const uint4*)(Whi + (size_t)n * ND + k0 + q * 8);
            uint4 lv = *(const uint4*)(Wlo + (size_t)n * ND + k0 + q * 8);
            *(uint4*)&Bs_hi[n][q * 8] = hv;
            *(uint4*)&Bs_lo[n][q * 8] = lv;
        }
        __syncthreads();

        #pragma unroll
        for (int kc = 0; kc < BK; kc += 16) {
            unsigned ah[4], al[4];
            int mr = 16 * w + qr;
            int kk = kc + 2 * qc;
            ah[0] = *(const unsigned*)&As_hi[mr][kk];
            ah[1] = *(const unsigned*)&As_hi[mr + 8][kk];
            ah[2] = *(const unsigned*)&As_hi[mr][kk + 8];
            ah[3] = *(const unsigned*)&As_hi[mr + 8][kk + 8];
            al[0] = *(const unsigned*)&As_lo[mr][kk];
            al[1] = *(const unsigned*)&As_lo[mr + 8][kk];
            al[2] = *(const unsigned*)&As_lo[mr][kk + 8];
            al[3] = *(const unsigned*)&As_lo[mr + 8][kk + 8];
            #pragma unroll
            for (int nt = 0; nt < 16; nt++) {
                int nr = nt * 8 + qr;
                unsigned bh[2], bl[2];
                bh[0] = *(const unsigned*)&Bs_hi[nr][kk];
                bh[1] = *(const unsigned*)&Bs_hi[nr][kk + 8];
                bl[0] = *(const unsigned*)&Bs_lo[nr][kk];
                bl[1] = *(const unsigned*)&Bs_lo[nr][kk + 8];
                mma_bf16(acc[nt], ah, bh);
                mma_bf16(acc[nt], ah, bl);
                mma_bf16(acc[nt], al, bh);
            }
        }
        __syncthreads();
    }

    // epilogue: bias + store (c0,c1 -> row r, cols c,c+1; c2,c3 -> row r+8)
    int gr0 = rowBase + 16 * w + qr;
    int gr1 = gr0 + 8;
    #pragma unroll
    for (int nt = 0; nt < 16; nt++) {
        int col = nt * 8 + 2 * qc;
        float b0 = __ldg(bias + col), b1 = __ldg(bias + col + 1);
        if (gr0 < NV)
            *(float2*)(C + (size_t)gr0 * ND + col) =
                make_float2(acc[nt][0] + b0, acc[nt][1] + b1);
        if (gr1 < NV)
            *(float2*)(C + (size_t)gr1 * ND + col) =
                make_float2(acc[nt][2] + b0, acc[nt][3] + b1);
    }
}

// ---------------- misc -------------------------------------------------------
__global__ void k_zero_stats() {
    int i = threadIdx.x;
    if (i < 2 * ND) g_stats[i] = 0.f;
}

__global__ void k_finalize() {
    int c = threadIdx.x;   // 128
    float mean = g_stats[c] * (1.0f / NV);
    float var  = g_stats[ND + c] * (1.0f / NV) - mean * mean;
    g_mr[c]      = mean;
    g_mr[ND + c] = rsqrtf(var + 1e-5f);
}

// ---------------- aggregate: out[v] = h0[v] + sum_{u in N(v)} y[u] -----------
__global__ void k_agg(const float* __restrict__ h0, const float* __restrict__ y,
                      float* __restrict__ out, int doStats) {
    int lane   = threadIdx.x & 31;
    int warp   = (blockIdx.x * blockDim.x + threadIdx.x) >> 5;
    int nwarps = (gridDim.x * blockDim.x) >> 5;

    float4 csum = make_float4(0.f, 0.f, 0.f, 0.f);
    float4 csq  = make_float4(0.f, 0.f, 0.f, 0.f);

    for (int v = warp; v < NV; v += nwarps) {
        float4 acc = ((const float4*)(h0 + (size_t)v * ND))[lane];
        int beg = g_rowptr[v], end = g_rowptr[v + 1];
        int j = beg;
        for (; j + 3 < end; j += 4) {
            int u0 = g_adj[j], u1 = g_adj[j + 1];
            int u2 = g_adj[j + 2], u3 = g_adj[j + 3];
            float4 a0 = ((const float4*)(y + (size_t)u0 * ND))[lane];
            float4 a1 = ((const float4*)(y + (size_t)u1 * ND))[lane];
            float4 a2 = ((const float4*)(y + (size_t)u2 * ND))[lane];
            float4 a3 = ((const float4*)(y + (size_t)u3 * ND))[lane];
            acc.x += (a0.x + a1.x) + (a2.x + a3.x);
            acc.y += (a0.y + a1.y) + (a2.y + a3.y);
            acc.z += (a0.z + a1.z) + (a2.z + a3.z);
            acc.w += (a0.w + a1.w) + (a2.w + a3.w);
        }
        for (; j < end; j++) {
            int u0 = g_adj[j];
            float4 a0 = ((const float4*)(y + (size_t)u0 * ND))[lane];
            acc.x += a0.x; acc.y += a0.y; acc.z += a0.z; acc.w += a0.w;
        }
        ((float4*)(out + (size_t)v * ND))[lane] = acc;
        if (doStats) {
            csum.x += acc.x; csum.y += acc.y; csum.z += acc.z; csum.w += acc.w;
            csq.x += acc.x * acc.x; csq.y += acc.y * acc.y;
            csq.z += acc.z * acc.z; csq.w += acc.w * acc.w;
        }
    }
    if (doStats) {
        int c = lane * 4;
        atomicAdd(&g_stats[c + 0], csum.x);
        atomicAdd(&g_stats[c + 1], csum.y);
        atomicAdd(&g_stats[c + 2], csum.z);
        atomicAdd(&g_stats[c + 3], csum.w);
        atomicAdd(&g_stats[ND + c + 0], csq.x);
        atomicAdd(&g_stats[ND + c + 1], csq.y);
        atomicAdd(&g_stats[ND + c + 2], csq.z);
        atomicAdd(&g_stats[ND + c + 3], csq.w);
    }
}

// ---------------- BN normalize + optional residual + ReLU --------------------
__global__ void k_norm(const float* __restrict__ h, float* __restrict__ f,
                       const float* __restrict__ gamma, const float* __restrict__ beta,
                       const float* __restrict__ res) {
    int i = blockIdx.x * blockDim.x + threadIdx.x;   // float4 index
    if (i >= NVD / 4) return;
    int col4 = i & (ND / 4 - 1);
    float4 hv = ((const float4*)h)[i];
    float4 mu = ((const float4*)g_mr)[col4];
    float4 rs = ((const float4*)(g_mr + ND))[col4];
    float4 ga = __ldg((const float4*)gamma + col4);
    float4 be = __ldg((const float4*)beta + col4);
    float4 o;
    o.x = (hv.x - mu.x) * rs.x * ga.x + be.x;
    o.y = (hv.y - mu.y) * rs.y * ga.y + be.y;
    o.z = (hv.z - mu.z) * rs.z * ga.z + be.z;
    o.w = (hv.w - mu.w) * rs.w * ga.w + be.w;
    if (res) {
        float4 rv = ((const float4*)res)[i];
        o.x += rv.x; o.y += rv.y; o.z += rv.z; o.w += rv.w;
    }
    o.x = fmaxf(o.x, 0.f); o.y = fmaxf(o.y, 0.f);
    o.z = fmaxf(o.z, 0.f); o.w = fmaxf(o.w, 0.f);
    ((float4*)f)[i] = o;
}

// ---------------- launch -----------------------------------------------------
extern "C" void kernel_launch(void* const* d_in, const int* in_sizes, int n_in,
                              void* d_out, int out_size) {
    const float* feat  = (const float*)d_in[0];
    const void*  edges = d_in[1];
    const float* W0    = (const float*)d_in[2];
    const float* b0    = (const float*)d_in[3];
    const float* W1    = (const float*)d_in[4];
    const float* b1    = (const float*)d_in[5];
    const float* gamma = (const float*)d_in[6];
    const float* beta  = (const float*)d_in[7];
    float*       out   = (float*)d_out;

    float* pf;  cudaGetSymbolAddress((void**)&pf,  g_f);
    float* ph0; cudaGetSymbolAddress((void**)&ph0, g_h0);
    float* py;  cudaGetSymbolAddress((void**)&py,  g_y);
    float* ph;  cudaGetSymbolAddress((void**)&ph,  g_h);
    __nv_bfloat16* pwh; cudaGetSymbolAddress((void**)&pwh, g_Whi);
    __nv_bfloat16* pwl; cudaGetSymbolAddress((void**)&pwl, g_Wlo);

    // CSR build + weight split (once per call)
    k_detect<<<1, 1>>>(edges);
    k_zero_deg<<<(NV + 255) / 256, 256>>>();
    k_wsplit<<<(8 * ND * ND + 255) / 256, 256>>>(W0, W1);
    k_count<<<(NE + 255) / 256, 256>>>(edges);
    k_bsum<<<NB, NTB>>>();
    k_bscan<<<1, 128>>>();
    k_apply<<<NB, NTB>>>();
    k_fill<<<(NE + 255) / 256, 256>>>(edges);

    const int gemmBlocks = (NV + BM - 1) / BM;   // 782
    const float* x = feat;
    for (int L = 0; L < 4; L++) {
        const __nv_bfloat16* wh0 = pwh + (size_t)(L * 2 + 0) * ND * ND;
        const __nv_bfloat16* wl0 = pwl + (size_t)(L * 2 + 0) * ND * ND;
        const __nv_bfloat16* wh1 = pwh + (size_t)(L * 2 + 1) * ND * ND;
        const __nv_bfloat16* wl1 = pwl + (size_t)(L * 2 + 1) * ND * ND;
        k_gemm_tc<<<gemmBlocks, 256>>>(x, wh0, wl0, b0 + L * ND, ph0);
        k_gemm_tc<<<gemmBlocks, 256>>>(x, wh1, wl1, b1 + L * ND, py);
        if (L < 3) {
            k_zero_stats<<<1, 256>>>();
            k_agg<<<2048, 256>>>(ph0, py, ph, 1);
            k_finalize<<<1, ND>>>();
            const float* res = (L == 2) ? feat : nullptr;
            k_norm<<<(NVD / 4 + 255) / 256, 256>>>(ph, pf, gamma + L * ND,
                                                   beta + L * ND, res);
            x = pf;
        } else {
            k_agg<<<2048, 256>>>(ph0, py, out, 0);
        }
    }
}

// round 6
// speedup vs baseline: 1.6025x; 1.0076x over previous
#include <cuda_runtime.h>
#include <cuda_bf16.h>

#define NV   100000
#define ND   128
#define NE   600000
#define NVD  (NV * ND)
#define NTB  1024
#define NB   ((NV + NTB - 1) / NTB)   // 98

// ---------------- scratch (device globals: no allocation allowed) ------------
__device__ float g_f[NVD];
__device__ float g_h0[NVD];
__device__ float g_y[NVD];
__device__ float g_h[NVD];
__device__ int   g_deg[NV];
__device__ int   g_rowptr[NV + 1];
__device__ int   g_cursor[NV];
__device__ int   g_adj[2 * NE];
__device__ float g_stats[2 * ND];
__device__ float g_mr[2 * ND];
__device__ int   g_is64;
__device__ int   g_bsum[NB];
__device__ int   g_boff[NB];
__device__ __nv_bfloat16 g_Whi[8 * ND * ND];  // [s][n][k], s = L*2+br
__device__ __nv_bfloat16 g_Wlo[8 * ND * ND];

// ---------------- edge dtype probe ------------------------------------------
__global__ void k_detect(const void* __restrict__ edges) {
    const long long* e = (const long long*)edges;
    int ok = 1;
    for (int i = 0; i < 16; i++) {
        long long v = e[i];
        if (v < 0 || v >= NV) ok = 0;
    }
    g_is64 = ok;
}

__device__ __forceinline__ void load_edge(const void* edges, int e, int& a, int& b) {
    if (g_is64) {
        longlong2 p = ((const longlong2*)edges)[e];
        a = (int)p.x; b = (int)p.y;
    } else {
        int2 p = ((const int2*)edges)[e];
        a = p.x; b = p.y;
    }
}

// ---------------- CSR build --------------------------------------------------
__global__ void k_zero_deg() {
    int i = blockIdx.x * blockDim.x + threadIdx.x;
    if (i < NV) g_deg[i] = 0;
}

__global__ void k_count(const void* __restrict__ edges) {
    int e = blockIdx.x * blockDim.x + threadIdx.x;
    if (e < NE) {
        int a, b;
        load_edge(edges, e, a, b);
        atomicAdd(&g_deg[a], 1);
        atomicAdd(&g_deg[b], 1);
    }
}

__global__ void k_bsum() {
    __shared__ int ws[32];
    int t = threadIdx.x, lane = t & 31, wid = t >> 5;
    int idx = blockIdx.x * NTB + t;
    int v = (idx < NV) ? g_deg[idx] : 0;
    #pragma unroll
    for (int off = 16; off > 0; off >>= 1)
        v += __shfl_down_sync(0xFFFFFFFFu, v, off);
    if (lane == 0) ws[wid] = v;
    __syncthreads();
    if (wid == 0) {
        int s = ws[lane];
        #pragma unroll
        for (int off = 16; off > 0; off >>= 1)
            s += __shfl_down_sync(0xFFFFFFFFu, s, off);
        if (lane == 0) g_bsum[blockIdx.x] = s;
    }
}

__global__ void k_bscan() {
    __shared__ int ws[4];
    int t = threadIdx.x, lane = t & 31, wid = t >> 5;
    int v = (t < NB) ? g_bsum[t] : 0;
    int inc = v;
    #pragma unroll
    for (int off = 1; off < 32; off <<= 1) {
        int x = __shfl_up_sync(0xFFFFFFFFu, inc, off);
        if (lane >= off) inc += x;
    }
    if (lane == 31) ws[wid] = inc;
    __syncthreads();
    int woff = 0;
    for (int w = 0; w < wid; w++) woff += ws[w];
    if (t < NB) g_boff[t] = woff + inc - v;
    if (t == 0) g_rowptr[NV] = 2 * NE;
}

__global__ void k_apply() {
    __shared__ int ws[32];
    int t = threadIdx.x, lane = t & 31, wid = t >> 5;
    int idx = blockIdx.x * NTB + t;
    int v = (idx < NV) ? g_deg[idx] : 0;
    int inc = v;
    #pragma unroll
    for (int off = 1; off < 32; off <<= 1) {
        int x = __shfl_up_sync(0xFFFFFFFFu, inc, off);
        if (lane >= off) inc += x;
    }
    if (lane == 31) ws[wid] = inc;
    __syncthreads();
    if (wid == 0) {
        int s = ws[lane];
        #pragma unroll
        for (int off = 1; off < 32; off <<= 1) {
            int x = __shfl_up_sync(0xFFFFFFFFu, s, off);
            if (lane >= off) s += x;
        }
        ws[lane] = s;
    }
    __syncthreads();
    int excl = g_boff[blockIdx.x] + ((wid > 0) ? ws[wid - 1] : 0) + inc - v;
    if (idx < NV) { g_rowptr[idx] = excl; g_cursor[idx] = excl; }
}

__global__ void k_fill(const void* __restrict__ edges) {
    int e = blockIdx.x * blockDim.x + threadIdx.x;
    if (e < NE) {
        int a, b;
        load_edge(edges, e, a, b);
        int pa = atomicAdd(&g_cursor[a], 1);
        g_adj[pa] = b;
        int pb = atomicAdd(&g_cursor[b], 1);
        g_adj[pb] = a;
    }
}

// ---------------- weight split into bf16 hi/lo -------------------------------
__global__ void k_wsplit(const float* __restrict__ W0, const float* __restrict__ W1) {
    int i = blockIdx.x * blockDim.x + threadIdx.x;
    if (i >= 8 * ND * ND) return;
    int s = i >> 14;             // 0..7
    int L = s >> 1, br = s & 1;
    int nk = i & (ND * ND - 1);
    const float* W = br ? W1 : W0;
    float w = W[(size_t)L * ND * ND + nk];
    __nv_bfloat16 hi = __float2bfloat16_rn(w);
    __nv_bfloat16 lo = __float2bfloat16_rn(w - __bfloat162float(hi));
    g_Whi[i] = hi;
    g_Wlo[i] = lo;
}

// ---------------- fused dual tensor-core GEMM --------------------------------
// C0[i,j] = sum_k A[i,k]*W0[j,k] + b0[j];  C1 likewise. Shared A staging.
#define BM 128
#define BK 32
#define LDA 40          // 80-byte rows: 16B-aligned, conflict-free 32-bit frags

__device__ __forceinline__ void mma_bf16(float* c, const unsigned* a, const unsigned* b) {
    asm volatile(
        "mma.sync.aligned.m16n8k16.row.col.f32.bf16.bf16.f32 "
        "{%0,%1,%2,%3}, {%4,%5,%6,%7}, {%8,%9}, {%0,%1,%2,%3};"
        : "+f"(c[0]), "+f"(c[1]), "+f"(c[2]), "+f"(c[3])
        : "r"(a[0]), "r"(a[1]), "r"(a[2]), "r"(a[3]), "r"(b[0]), "r"(b[1]));
}

#define SM_AHI 0
#define SM_ALO (128 * LDA)
#define SM_B0H (2 * 128 * LDA)
#define SM_B0L (3 * 128 * LDA)
#define SM_B1H (4 * 128 * LDA)
#define SM_B1L (5 * 128 * LDA)
#define SMEM_HALVES (6 * 128 * LDA)   // 30720 halves = 61440 B

__global__ __launch_bounds__(512, 1)
void k_gemm_dual(const float* __restrict__ A,
                 const __nv_bfloat16* __restrict__ Whi0,
                 const __nv_bfloat16* __restrict__ Wlo0,
                 const __nv_bfloat16* __restrict__ Whi1,
                 const __nv_bfloat16* __restrict__ Wlo1,
                 const float* __restrict__ bias0,
                 const float* __restrict__ bias1,
                 float* __restrict__ C0, float* __restrict__ C1) {
    extern __shared__ __nv_bfloat16 sm[];
    int tid = threadIdx.x;            // 512
    int w    = tid >> 5;              // 0..15
    int lane = tid & 31;
    int qr = lane >> 2, qc = lane & 3;
    int half = w >> 3;                // n-half: 0 -> cols 0..63, 1 -> 64..127
    int wm   = w & 7;                 // m rows [16wm, 16wm+16)
    int rowBase = blockIdx.x * BM;

    float acc0[8][4], acc1[8][4];
    #pragma unroll
    for (int nt = 0; nt < 8; nt++)
        #pragma unroll
        for (int j = 0; j < 4; j++) { acc0[nt][j] = 0.f; acc1[nt][j] = 0.f; }

    for (int k0 = 0; k0 < ND; k0 += BK) {
        // stage A tile [128][32] fp32 -> bf16 hi/lo (1024 float4 slots, 2/thread)
        #pragma unroll
        for (int i = 0; i < 2; i++) {
            int s = i * 512 + tid;
            int r = s >> 3;
            int q = s & 7;
            float4 av = make_float4(0.f, 0.f, 0.f, 0.f);
            if (rowBase + r < NV)
                av = *(const float4*)(A + (size_t)(rowBase + r) * ND + k0 + q * 4);
            float vv[4] = {av.x, av.y, av.z, av.w};
            __nv_bfloat16 h[4], l[4];
            #pragma unroll
            for (int j = 0; j < 4; j++) {
                h[j] = __float2bfloat16_rn(vv[j]);
                l[j] = __float2bfloat16_rn(vv[j] - __bfloat162float(h[j]));
            }
            __nv_bfloat16* ah = sm + SM_AHI + r * LDA + q * 4;
            __nv_bfloat16* al = sm + SM_ALO + r * LDA + q * 4;
            *(__nv_bfloat162*)(ah)     = __nv_bfloat162{h[0], h[1]};
            *(__nv_bfloat162*)(ah + 2) = __nv_bfloat162{h[2], h[3]};
            *(__nv_bfloat162*)(al)     = __nv_bfloat162{l[0], l[1]};
            *(__nv_bfloat162*)(al + 2) = __nv_bfloat162{l[2], l[3]};
        }
        // stage both W tiles (pre-split): 512 uint4 slots per plane, 1/thread
        {
            int n = tid >> 2;
            int q = (tid & 3) * 8;
            size_t goff = (size_t)n * ND + k0 + q;
            int soff = n * LDA + q;
            *(uint4*)(sm + SM_B0H + soff) = *(const uint4*)(Whi0 + goff);
            *(uint4*)(sm + SM_B0L + soff) = *(const uint4*)(Wlo0 + goff);
            *(uint4*)(sm + SM_B1H + soff) = *(const uint4*)(Whi1 + goff);
            *(uint4*)(sm + SM_B1L + soff) = *(const uint4*)(Wlo1 + goff);
        }
        __syncthreads();

        int mr = 16 * wm + qr;
        #pragma unroll
        for (int kc = 0; kc < BK; kc += 16) {
            int kk = kc + 2 * qc;
            unsigned ah[4], al[4];
            ah[0] = *(const unsigned*)(sm + SM_AHI + mr * LDA + kk);
            ah[1] = *(const unsigned*)(sm + SM_AHI + (mr + 8) * LDA + kk);
            ah[2] = *(const unsigned*)(sm + SM_AHI + mr * LDA + kk + 8);
            ah[3] = *(const unsigned*)(sm + SM_AHI + (mr + 8) * LDA + kk + 8);
            al[0] = *(const unsigned*)(sm + SM_ALO + mr * LDA + kk);
            al[1] = *(const unsigned*)(sm + SM_ALO + (mr + 8) * LDA + kk);
            al[2] = *(const unsigned*)(sm + SM_ALO + mr * LDA + kk + 8);
            al[3] = *(const unsigned*)(sm + SM_ALO + (mr + 8) * LDA + kk + 8);
            #pragma unroll
            for (int nt = 0; nt < 8; nt++) {
                int nr = half * 64 + nt * 8 + qr;
                unsigned b0h[2], b0l[2], b1h[2], b1l[2];
                b0h[0] = *(const unsigned*)(sm + SM_B0H + nr * LDA + kk);
                b0h[1] = *(const unsigned*)(sm + SM_B0H + nr * LDA + kk + 8);
                b0l[0] = *(const unsigned*)(sm + SM_B0L + nr * LDA + kk);
                b0l[1] = *(const unsigned*)(sm + SM_B0L + nr * LDA + kk + 8);
                b1h[0] = *(const unsigned*)(sm + SM_B1H + nr * LDA + kk);
                b1h[1] = *(const unsigned*)(sm + SM_B1H + nr * LDA + kk + 8);
                b1l[0] = *(const unsigned*)(sm + SM_B1L + nr * LDA + kk);
                b1l[1] = *(const unsigned*)(sm + SM_B1L + nr * LDA + kk + 8);
                mma_bf16(acc0[nt], ah, b0h);
                mma_bf16(acc0[nt], ah, b0l);
                mma_bf16(acc0[nt], al, b0h);
                mma_bf16(acc1[nt], ah, b1h);
                mma_bf16(acc1[nt], ah, b1l);
                mma_bf16(acc1[nt], al, b1h);
            }
        }
        __syncthreads();
    }

    int gr0 = rowBase + 16 * wm + qr;
    int gr1 = gr0 + 8;
    #pragma unroll
    for (int nt = 0; nt < 8; nt++) {
        int col = half * 64 + nt * 8 + 2 * qc;
        float p0 = __ldg(bias0 + col), p1 = __ldg(bias0 + col + 1);
        float q0 = __ldg(bias1 + col), q1 = __ldg(bias1 + col + 1);
        if (gr0 < NV) {
            *(float2*)(C0 + (size_t)gr0 * ND + col) =
                make_float2(acc0[nt][0] + p0, acc0[nt][1] + p1);
            *(float2*)(C1 + (size_t)gr0 * ND + col) =
                make_float2(acc1[nt][0] + q0, acc1[nt][1] + q1);
        }
        if (gr1 < NV) {
            *(float2*)(C0 + (size_t)gr1 * ND + col) =
                make_float2(acc0[nt][2] + p0, acc0[nt][3] + p1);
            *(float2*)(C1 + (size_t)gr1 * ND + col) =
                make_float2(acc1[nt][2] + q0, acc1[nt][3] + q1);
        }
    }
}

// ---------------- misc -------------------------------------------------------
__global__ void k_zero_stats() {
    int i = threadIdx.x;
    if (i < 2 * ND) g_stats[i] = 0.f;
}

__global__ void k_finalize() {
    int c = threadIdx.x;   // 128
    float mean = g_stats[c] * (1.0f / NV);
    float var  = g_stats[ND + c] * (1.0f / NV) - mean * mean;
    g_mr[c]      = mean;
    g_mr[ND + c] = rsqrtf(var + 1e-5f);
}

// ---------------- aggregate: out[v] = h0[v] + sum_{u in N(v)} y[u] -----------
__global__ void k_agg(const float* __restrict__ h0, const float* __restrict__ y,
                      float* __restrict__ out, int doStats) {
    int lane   = threadIdx.x & 31;
    int warp   = (blockIdx.x * blockDim.x + threadIdx.x) >> 5;
    int nwarps = (gridDim.x * blockDim.x) >> 5;

    float4 csum = make_float4(0.f, 0.f, 0.f, 0.f);
    float4 csq  = make_float4(0.f, 0.f, 0.f, 0.f);

    for (int v = warp; v < NV; v += nwarps) {
        float4 acc = ((const float4*)(h0 + (size_t)v * ND))[lane];
        int beg = g_rowptr[v], end = g_rowptr[v + 1];
        int j = beg;
        for (; j + 7 < end; j += 8) {
            float4 a[8];
            #pragma unroll
            for (int t = 0; t < 8; t++) {
                int u = g_adj[j + t];
                a[t] = ((const float4*)(y + (size_t)u * ND))[lane];
            }
            acc.x += ((a[0].x + a[1].x) + (a[2].x + a[3].x)) +
                     ((a[4].x + a[5].x) + (a[6].x + a[7].x));
            acc.y += ((a[0].y + a[1].y) + (a[2].y + a[3].y)) +
                     ((a[4].y + a[5].y) + (a[6].y + a[7].y));
            acc.z += ((a[0].z + a[1].z) + (a[2].z + a[3].z)) +
                     ((a[4].z + a[5].z) + (a[6].z + a[7].z));
            acc.w += ((a[0].w + a[1].w) + (a[2].w + a[3].w)) +
                     ((a[4].w + a[5].w) + (a[6].w + a[7].w));
        }
        for (; j + 1 < end; j += 2) {
            int u0 = g_adj[j], u1 = g_adj[j + 1];
            float4 a0 = ((const float4*)(y + (size_t)u0 * ND))[lane];
            float4 a1 = ((const float4*)(y + (size_t)u1 * ND))[lane];
            acc.x += a0.x + a1.x; acc.y += a0.y + a1.y;
            acc.z += a0.z + a1.z; acc.w += a0.w + a1.w;
        }
        if (j < end) {
            int u0 = g_adj[j];
            float4 a0 = ((const float4*)(y + (size_t)u0 * ND))[lane];
            acc.x += a0.x; acc.y += a0.y; acc.z += a0.z; acc.w += a0.w;
        }
        ((float4*)(out + (size_t)v * ND))[lane] = acc;
        if (doStats) {
            csum.x += acc.x; csum.y += acc.y; csum.z += acc.z; csum.w += acc.w;
            csq.x += acc.x * acc.x; csq.y += acc.y * acc.y;
            csq.z += acc.z * acc.z; csq.w += acc.w * acc.w;
        }
    }
    if (doStats) {
        int c = lane * 4;
        atomicAdd(&g_stats[c + 0], csum.x);
        atomicAdd(&g_stats[c + 1], csum.y);
        atomicAdd(&g_stats[c + 2], csum.z);
        atomicAdd(&g_stats[c + 3], csum.w);
        atomicAdd(&g_stats[ND + c + 0], csq.x);
        atomicAdd(&g_stats[ND + c + 1], csq.y);
        atomicAdd(&g_stats[ND + c + 2], csq.z);
        atomicAdd(&g_stats[ND + c + 3], csq.w);
    }
}

// ---------------- BN normalize + optional residual + ReLU --------------------
__global__ void k_norm(const float* __restrict__ h, float* __restrict__ f,
                       const float* __restrict__ gamma, const float* __restrict__ beta,
                       const float* __restrict__ res) {
    int i = blockIdx.x * blockDim.x + threadIdx.x;
    if (i >= NVD / 4) return;
    int col4 = i & (ND / 4 - 1);
    float4 hv = ((const float4*)h)[i];
    float4 mu = ((const float4*)g_mr)[col4];
    float4 rs = ((const float4*)(g_mr + ND))[col4];
    float4 ga = __ldg((const float4*)gamma + col4);
    float4 be = __ldg((const float4*)beta + col4);
    float4 o;
    o.x = (hv.x - mu.x) * rs.x * ga.x + be.x;
    o.y = (hv.y - mu.y) * rs.y * ga.y + be.y;
    o.z = (hv.z - mu.z) * rs.z * ga.z + be.z;
    o.w = (hv.w - mu.w) * rs.w * ga.w + be.w;
    if (res) {
        float4 rv = ((const float4*)res)[i];
        o.x += rv.x; o.y += rv.y; o.z += rv.z; o.w += rv.w;
    }
    o.x = fmaxf(o.x, 0.f); o.y = fmaxf(o.y, 0.f);
    o.z = fmaxf(o.z, 0.f); o.w = fmaxf(o.w, 0.f);
    ((float4*)f)[i] = o;
}

// ---------------- launch -----------------------------------------------------
extern "C" void kernel_launch(void* const* d_in, const int* in_sizes, int n_in,
                              void* d_out, int out_size) {
    const float* feat  = (const float*)d_in[0];
    const void*  edges = d_in[1];
    const float* W0    = (const float*)d_in[2];
    const float* b0    = (const float*)d_in[3];
    const float* W1    = (const float*)d_in[4];
    const float* b1    = (const float*)d_in[5];
    const float* gamma = (const float*)d_in[6];
    const float* beta  = (const float*)d_in[7];
    float*       out   = (float*)d_out;

    float* pf;  cudaGetSymbolAddress((void**)&pf,  g_f);
    float* ph0; cudaGetSymbolAddress((void**)&ph0, g_h0);
    float* py;  cudaGetSymbolAddress((void**)&py,  g_y);
    float* ph;  cudaGetSymbolAddress((void**)&ph,  g_h);
    __nv_bfloat16* pwh; cudaGetSymbolAddress((void**)&pwh, g_Whi);
    __nv_bfloat16* pwl; cudaGetSymbolAddress((void**)&pwl, g_Wlo);

    const int smemBytes = SMEM_HALVES * (int)sizeof(__nv_bfloat16);  // 61440
    cudaFuncSetAttribute(k_gemm_dual, cudaFuncAttributeMaxDynamicSharedMemorySize,
                         smemBytes);

    // CSR build + weight split (once per call)
    k_detect<<<1, 1>>>(edges);
    k_zero_deg<<<(NV + 255) / 256, 256>>>();
    k_wsplit<<<(8 * ND * ND + 255) / 256, 256>>>(W0, W1);
    k_count<<<(NE + 255) / 256, 256>>>(edges);
    k_bsum<<<NB, NTB>>>();
    k_bscan<<<1, 128>>>();
    k_apply<<<NB, NTB>>>();
    k_fill<<<(NE + 255) / 256, 256>>>(edges);

    const int gemmBlocks = (NV + BM - 1) / BM;   // 782
    const float* x = feat;
    for (int L = 0; L < 4; L++) {
        const __nv_bfloat16* wh0 = pwh + (size_t)(L * 2 + 0) * ND * ND;
        const __nv_bfloat16* wl0 = pwl + (size_t)(L * 2 + 0) * ND * ND;
        const __nv_bfloat16* wh1 = pwh + (size_t)(L * 2 + 1) * ND * ND;
        const __nv_bfloat16* wl1 = pwl + (size_t)(L * 2 + 1) * ND * ND;
        k_gemm_dual<<<gemmBlocks, 512, smemBytes>>>(x, wh0, wl0, wh1, wl1,
                                                    b0 + L * ND, b1 + L * ND,
                                                    ph0, py);
        if (L < 3) {
            k_zero_stats<<<1, 256>>>();
            k_agg<<<2048, 256>>>(ph0, py, ph, 1);
            k_finalize<<<1, ND>>>();
            const float* res = (L == 2) ? feat : nullptr;
            k_norm<<<(NVD / 4 + 255) / 256, 256>>>(ph, pf, gamma + L * ND,
                                                   beta + L * ND, res);
            x = pf;
        } else {
            k_agg<<<2048, 256>>>(ph0, py, out, 0);
        }
    }
}